// round 6
// baseline (speedup 1.0000x reference)
#include <cuda_runtime.h>

#define BB  32
#define TT  200
#define TM  400
#define EE  256
#define HH  256
#define ENCX 512
#define DECX 1024
#define OUTX 80

#define SOFF (BB*TM*OUTX)
#define AOFF (SOFF + BB*TM)

#define NCTA 148
#define NTHR 256

// dynamic smem layout (floats)
#define WS_OFF 0            // 28 rows x 1616 = 45248 floats (decoder gate weights)
#define XS_OFF 45248        // 4096 floats (128 k x 32 b staging)
#define V_OFF  49344        // 1024 floats (attention v)
#define SMEM_F 50368
#define SMEM_BYTES (SMEM_F*4)

// ---------------- device scratch ----------------
__device__ __align__(16) float g_enc_out[BB*TT*ENCX];
__device__ __align__(16) float g_proj[BB*TT*DECX];
__device__ __align__(16) float g_henc[2][2][HH*BB];
__device__ __align__(16) float g_cenc[2][HH*BB];
__device__ __align__(16) float g_hproj[BB*DECX];
__device__ __align__(16) float g_scores[BB*TT];
__device__ __align__(16) float g_ctx[ENCX*BB];
__device__ __align__(16) float g_hdec[2][DECX*BB];
__device__ __align__(16) float g_cdec[DECX*BB];

__device__ unsigned g_cnt = 0;
__device__ unsigned g_gen = 0;

__device__ __forceinline__ float sigf(float x) {
    return __fdividef(1.f, 1.f + __expf(-x));
}
__device__ __forceinline__ float tanhx(float x) {
    return 1.f - __fdividef(2.f, __expf(2.f * x) + 1.f);
}

__device__ __forceinline__ void gsync() {
    __syncthreads();
    if (threadIdx.x == 0) {
        __threadfence();
        unsigned g = g_gen;
        if (atomicAdd(&g_cnt, 1u) == gridDim.x - 1) {
            g_cnt = 0;
            __threadfence();
            atomicExch(&g_gen, g + 1u);
        } else {
            while (((volatile unsigned*)&g_gen)[0] == g) { }
        }
        __threadfence();
    }
    __syncthreads();
}

__global__ void __launch_bounds__(NTHR, 1) k_mega(
    const int* __restrict__ text, const float* __restrict__ melt,
    const float* __restrict__ emb,
    const float* __restrict__ efWih, const float* __restrict__ efWhh, const float* __restrict__ efb,
    const float* __restrict__ ebWih, const float* __restrict__ ebWhh, const float* __restrict__ ebb,
    const float* __restrict__ Ws, const float* __restrict__ bs, const float* __restrict__ v,
    const float* __restrict__ dWih, const float* __restrict__ dWhh, const float* __restrict__ db,
    const float* __restrict__ Wout, const float* __restrict__ bout,
    const float* __restrict__ Wstop, const float* __restrict__ bstop,
    float* __restrict__ out)
{
    extern __shared__ float sm[];
    const int cta  = blockIdx.x;
    const int tid  = threadIdx.x;
    const int w    = tid >> 5;
    const int lane = tid & 31;

    // ---------- P0: zero states ----------
    {
        int gi = cta * NTHR + tid, gn = NCTA * NTHR;
        for (int j = gi; j < 2*2*HH*BB; j += gn) ((float*)g_henc)[j] = 0.f;
        for (int j = gi; j < 2*HH*BB;   j += gn) ((float*)g_cenc)[j] = 0.f;
        for (int j = gi; j < BB*DECX;   j += gn) g_hproj[j] = 0.f;
        for (int j = gi; j < 2*DECX*BB; j += gn) ((float*)g_hdec)[j] = 0.f;
        for (int j = gi; j < DECX*BB;   j += gn) g_cdec[j] = 0.f;
    }
    gsync();

    // ---------- encoder: 200 steps, CTAs 0..63 ----------
    for (int t = 0; t < TT; t++) {
        if (cta < 64) {
            const int dir = cta >> 5;
            const int bx  = cta & 31;
            const int u   = bx * 8 + w;
            const int p   = t & 1;
            const float* Wih  = dir ? ebWih : efWih;
            const float* Whh  = dir ? ebWhh : efWhh;
            const float* bias = dir ? ebb   : efb;
            const int tt = dir ? (TT - 1 - t) : t;

            float* xs_e = sm;            // [128][33]
            float* hs_e = sm + 128*33;   // [128][32]

            float a0 = bias[0*HH+u], a1 = bias[1*HH+u], a2 = bias[2*HH+u], a3 = bias[3*HH+u];
            const float* wi0 = Wih + (0*HH+u)*EE; const float* wi1 = Wih + (1*HH+u)*EE;
            const float* wi2 = Wih + (2*HH+u)*EE; const float* wi3 = Wih + (3*HH+u)*EE;
            const float* wh0 = Whh + (0*HH+u)*HH; const float* wh1 = Whh + (1*HH+u)*HH;
            const float* wh2 = Whh + (2*HH+u)*HH; const float* wh3 = Whh + (3*HH+u)*HH;
            const float* hsrc = g_henc[dir][p];

            for (int kc = 0; kc < EE; kc += 128) {
                #pragma unroll
                for (int r = 0; r < 4; r++) {
                    int b2  = w * 4 + r;
                    int tok = text[b2 * TT + tt];
                    float4 v4 = *(const float4*)(emb + tok * EE + kc + lane * 4);
                    xs_e[(lane*4+0)*33+b2] = v4.x; xs_e[(lane*4+1)*33+b2] = v4.y;
                    xs_e[(lane*4+2)*33+b2] = v4.z; xs_e[(lane*4+3)*33+b2] = v4.w;
                }
                {
                    const float4* s4 = (const float4*)(hsrc + kc * 32);
                    float4* d4 = (float4*)hs_e;
                    for (int i2 = tid; i2 < 1024; i2 += NTHR) d4[i2] = __ldcg(s4 + i2);
                }
                __syncthreads();
                #pragma unroll 8
                for (int k = 0; k < 128; k += 4) {
                    float x0 = xs_e[(k+0)*33+lane], x1 = xs_e[(k+1)*33+lane];
                    float x2 = xs_e[(k+2)*33+lane], x3 = xs_e[(k+3)*33+lane];
                    float h0 = hs_e[(k+0)*32+lane], h1 = hs_e[(k+1)*32+lane];
                    float h2 = hs_e[(k+2)*32+lane], h3 = hs_e[(k+3)*32+lane];
                    float4 a, c;
                    a = *(const float4*)(wi0+kc+k); c = *(const float4*)(wh0+kc+k);
                    a0 += a.x*x0+a.y*x1+a.z*x2+a.w*x3 + c.x*h0+c.y*h1+c.z*h2+c.w*h3;
                    a = *(const float4*)(wi1+kc+k); c = *(const float4*)(wh1+kc+k);
                    a1 += a.x*x0+a.y*x1+a.z*x2+a.w*x3 + c.x*h0+c.y*h1+c.z*h2+c.w*h3;
                    a = *(const float4*)(wi2+kc+k); c = *(const float4*)(wh2+kc+k);
                    a2 += a.x*x0+a.y*x1+a.z*x2+a.w*x3 + c.x*h0+c.y*h1+c.z*h2+c.w*h3;
                    a = *(const float4*)(wi3+kc+k); c = *(const float4*)(wh3+kc+k);
                    a3 += a.x*x0+a.y*x1+a.z*x2+a.w*x3 + c.x*h0+c.y*h1+c.z*h2+c.w*h3;
                }
                __syncthreads();
            }
            float cc = g_cenc[dir][u*32 + lane];
            float cn = sigf(a1) * cc + sigf(a0) * tanhx(a2);
            float hn = sigf(a3) * tanhx(cn);
            g_cenc[dir][u*32 + lane] = cn;
            g_henc[dir][1 - p][u*32 + lane] = hn;
            g_enc_out[(lane*TT + tt)*ENCX + dir*HH + u] = hn;
        }
        gsync();
    }

    // ---------- proj_enc GEMM: 1600 tiles over 148 CTAs ----------
    {
        float* As = sm;           // [16][65]
        float* Bs = sm + 1040;    // [16][65]
        const int tx = tid & 15, ty = tid >> 4;
        const int rr = tid >> 2, q = tid & 3;
        for (int tl = cta; tl < 1600; tl += NCTA) {
            const int n0 = (tl & 15) * 64, m0 = (tl >> 4) * 64;
            float acc[4][4];
            #pragma unroll
            for (int i = 0; i < 4; i++)
                #pragma unroll
                for (int j = 0; j < 4; j++) acc[i][j] = 0.f;
            for (int k0 = 0; k0 < ENCX; k0 += 16) {
                float4 a4 = *(const float4*)(g_enc_out + (m0 + rr)*ENCX + k0 + q*4);
                As[(q*4+0)*65+rr] = a4.x; As[(q*4+1)*65+rr] = a4.y;
                As[(q*4+2)*65+rr] = a4.z; As[(q*4+3)*65+rr] = a4.w;
                float4 b4 = *(const float4*)(Ws + (n0 + rr)*(ENCX+DECX) + k0 + q*4);
                Bs[(q*4+0)*65+rr] = b4.x; Bs[(q*4+1)*65+rr] = b4.y;
                Bs[(q*4+2)*65+rr] = b4.z; Bs[(q*4+3)*65+rr] = b4.w;
                __syncthreads();
                #pragma unroll
                for (int k = 0; k < 16; k++) {
                    float ar[4], br[4];
                    #pragma unroll
                    for (int i = 0; i < 4; i++) { ar[i] = As[k*65+ty*4+i]; br[i] = Bs[k*65+tx*4+i]; }
                    #pragma unroll
                    for (int i = 0; i < 4; i++)
                        #pragma unroll
                        for (int j = 0; j < 4; j++) acc[i][j] += ar[i] * br[j];
                }
                __syncthreads();
            }
            #pragma unroll
            for (int i = 0; i < 4; i++)
                #pragma unroll
                for (int j = 0; j < 4; j++)
                    g_proj[(m0 + ty*4 + i)*DECX + n0 + tx*4 + j] = acc[i][j] + bs[n0 + tx*4 + j];
        }
        __syncthreads();
    }

    // ---------- preload decoder gate weights + v into smem ----------
    {
        for (int i = tid; i < 28*1616; i += NTHR) {
            int r = i / 1616, k = i - r*1616;
            int u = cta*7 + (r >> 2), g = r & 3;
            float val = 0.f;
            if (u < DECX)
                val = (k < 592) ? dWih[(g*DECX+u)*592 + k] : dWhh[(g*DECX+u)*DECX + (k-592)];
            sm[WS_OFF + i] = val;
        }
        for (int i = tid; i < DECX; i += NTHR) sm[V_OFF + i] = v[i];
        __syncthreads();
    }
    gsync();

    // ---------- decoder: 400 steps ----------
    float* xs = sm + XS_OFF;
    const float* vs = sm + V_OFF;

    for (int t = 0; t < TM; t++) {
        const int p = t & 1;

        // --- A: scores[b,s] = sum_d v[d]*tanh(proj + hproj) ---
        for (int pp = cta*8 + w; pp < BB*TT; pp += NCTA*8) {
            const int b = pp & 31, s = pp >> 5;
            const float* pr = g_proj + (b*TT + s)*DECX;
            const float* hp = g_hproj + b*DECX;
            float acc = 0.f;
            #pragma unroll 4
            for (int d = lane; d < DECX; d += 32)
                acc += vs[d] * tanhx(pr[d] + __ldcg(hp + d));
            #pragma unroll
            for (int o = 16; o; o >>= 1) acc += __shfl_xor_sync(0xffffffffu, acc, o);
            if (lane == 0) g_scores[b*TT + s] = acc;
        }
        gsync();

        // --- B: softmax + context (CTA b < 32) ---
        if (cta < BB) {
            const int b = cta;
            float* wb  = sm + XS_OFF;        // [200]
            float* red = sm + XS_OFF + 256;  // [256]
            float m = -1e30f;
            for (int s = tid; s < TT; s += NTHR) m = fmaxf(m, __ldcg(g_scores + b*TT + s));
            red[tid] = m; __syncthreads();
            for (int st = 128; st > 0; st >>= 1) {
                if (tid < st) red[tid] = fmaxf(red[tid], red[tid + st]);
                __syncthreads();
            }
            m = red[0]; __syncthreads();
            float sum = 0.f;
            for (int s = tid; s < TT; s += NTHR) {
                float e2 = __expf(__ldcg(g_scores + b*TT + s) - m);
                wb[s] = e2; sum += e2;
            }
            red[tid] = sum; __syncthreads();
            for (int st = 128; st > 0; st >>= 1) {
                if (tid < st) red[tid] += red[tid + st];
                __syncthreads();
            }
            float inv = __fdividef(1.f, red[0]);
            __syncthreads();
            for (int s = tid; s < TT; s += NTHR) {
                float ww = wb[s] * inv; wb[s] = ww;
                out[AOFF + (b*TM + t)*TT + s] = ww;
            }
            __syncthreads();
            const int e0 = tid, e1 = tid + NTHR;
            float c0 = 0.f, c1 = 0.f;
            #pragma unroll 2
            for (int s = 0; s < TT; s++) {
                float ww = wb[s];
                const float* er = g_enc_out + (b*TT + s)*ENCX;
                c0 += ww * er[e0];
                c1 += ww * er[e1];
            }
            g_ctx[e0*32 + b] = c0;
            g_ctx[e1*32 + b] = c1;
        }
        gsync();

        // --- C: gates GEMM + LSTM (weights in smem) ---
        {
            const int u = cta*7 + w;
            const bool act = (w < 7) && (u < DECX);
            const float* wr = sm + WS_OFF + (w*4)*1616;
            float a0 = 0.f, a1 = 0.f, a2 = 0.f, a3 = 0.f;
            if (act) {
                a0 = db[0*DECX+u]; a1 = db[1*DECX+u];
                a2 = db[2*DECX+u]; a3 = db[3*DECX+u];
            }
            // chunk 0: mel (teacher-forced input), len 80, xoff 0
            for (int i = tid; i < OUTX*BB; i += NTHR) {
                int b2 = i & 31, e = i >> 5;
                xs[i] = (t == 0) ? 0.f : melt[(b2*TM + (t-1))*OUTX + e];
            }
            __syncthreads();
            if (act) {
                #pragma unroll 5
                for (int k = 0; k < OUTX; k += 4) {
                    float x0 = xs[(k+0)*32+lane], x1 = xs[(k+1)*32+lane];
                    float x2 = xs[(k+2)*32+lane], x3 = xs[(k+3)*32+lane];
                    float4 q;
                    q = *(const float4*)(wr + 0*1616 + k); a0 += q.x*x0+q.y*x1+q.z*x2+q.w*x3;
                    q = *(const float4*)(wr + 1*1616 + k); a1 += q.x*x0+q.y*x1+q.z*x2+q.w*x3;
                    q = *(const float4*)(wr + 2*1616 + k); a2 += q.x*x0+q.y*x1+q.z*x2+q.w*x3;
                    q = *(const float4*)(wr + 3*1616 + k); a3 += q.x*x0+q.y*x1+q.z*x2+q.w*x3;
                }
            }
            __syncthreads();
            // chunks 1..12: ctx (4) then h (8), len 128 each
            for (int c = 1; c <= 12; c++) {
                const float* src = (c <= 4) ? (g_ctx + (c-1)*4096)
                                            : (g_hdec[p] + (c-5)*4096);
                const float4* s4 = (const float4*)src;
                float4* d4 = (float4*)xs;
                for (int i = tid; i < 1024; i += NTHR) d4[i] = __ldcg(s4 + i);
                __syncthreads();
                if (act) {
                    const int xoff = OUTX + (c-1)*128;
                    #pragma unroll 8
                    for (int k = 0; k < 128; k += 4) {
                        float x0 = xs[(k+0)*32+lane], x1 = xs[(k+1)*32+lane];
                        float x2 = xs[(k+2)*32+lane], x3 = xs[(k+3)*32+lane];
                        float4 q;
                        q = *(const float4*)(wr + 0*1616 + xoff + k); a0 += q.x*x0+q.y*x1+q.z*x2+q.w*x3;
                        q = *(const float4*)(wr + 1*1616 + xoff + k); a1 += q.x*x0+q.y*x1+q.z*x2+q.w*x3;
                        q = *(const float4*)(wr + 2*1616 + xoff + k); a2 += q.x*x0+q.y*x1+q.z*x2+q.w*x3;
                        q = *(const float4*)(wr + 3*1616 + xoff + k); a3 += q.x*x0+q.y*x1+q.z*x2+q.w*x3;
                    }
                }
                __syncthreads();
            }
            if (act) {
                float cc = g_cdec[u*32 + lane];
                float cn = sigf(a1) * cc + sigf(a0) * tanhx(a2);
                float hn = sigf(a3) * tanhx(cn);
                g_cdec[u*32 + lane] = cn;
                g_hdec[1 - p][u*32 + lane] = hn;
            }
        }
        gsync();

        // --- D: hproj / mel / stop from new h ---
        {
            const int r = cta*8 + w;
            const float* wrow = (r < DECX) ? (Ws + r*(ENCX+DECX) + ENCX)
                              : (r < DECX+OUTX) ? (Wout + (r-DECX)*DECX)
                              : Wstop;
            const bool act = (r <= DECX + OUTX);
            float acc = 0.f;
            const float* hsrc = g_hdec[1 - p];
            for (int c = 0; c < 8; c++) {
                const float4* s4 = (const float4*)(hsrc + c*4096);
                float4* d4 = (float4*)xs;
                for (int i = tid; i < 1024; i += NTHR) d4[i] = __ldcg(s4 + i);
                __syncthreads();
                if (act) {
                    #pragma unroll 8
                    for (int k = 0; k < 128; k += 4) {
                        float4 q = *(const float4*)(wrow + c*128 + k);
                        acc += q.x*xs[(k+0)*32+lane] + q.y*xs[(k+1)*32+lane]
                             + q.z*xs[(k+2)*32+lane] + q.w*xs[(k+3)*32+lane];
                    }
                }
                __syncthreads();
            }
            if (r < DECX) g_hproj[lane*DECX + r] = acc;
            else if (r < DECX + OUTX) out[(lane*TM + t)*OUTX + (r - DECX)] = acc + bout[r - DECX];
            else if (r == DECX + OUTX) out[SOFF + lane*TM + t] = sigf(acc + bstop[0]);
        }
        gsync();
    }
}

extern "C" void kernel_launch(void* const* d_in, const int* in_sizes, int n_in,
                              void* d_out, int out_size)
{
    const int*   text  = (const int*)d_in[0];
    const float* melt  = (const float*)d_in[1];
    const float* emb   = (const float*)d_in[2];
    const float* efWih = (const float*)d_in[3];
    const float* efWhh = (const float*)d_in[4];
    const float* efb   = (const float*)d_in[5];
    const float* ebWih = (const float*)d_in[6];
    const float* ebWhh = (const float*)d_in[7];
    const float* ebb   = (const float*)d_in[8];
    const float* Ws    = (const float*)d_in[9];
    const float* bs    = (const float*)d_in[10];
    const float* v     = (const float*)d_in[11];
    const float* dWih  = (const float*)d_in[12];
    const float* dWhh  = (const float*)d_in[13];
    const float* db    = (const float*)d_in[14];
    const float* Wout  = (const float*)d_in[15];
    const float* bout  = (const float*)d_in[16];
    const float* Wstop = (const float*)d_in[17];
    const float* bstop = (const float*)d_in[18];
    float* out = (float*)d_out;

    static int smem_set = 0;
    if (!smem_set) {
        cudaFuncSetAttribute(k_mega, cudaFuncAttributeMaxDynamicSharedMemorySize, SMEM_BYTES);
        smem_set = 1;
    }
    k_mega<<<NCTA, NTHR, SMEM_BYTES>>>(text, melt, emb, efWih, efWhh, efb,
                                       ebWih, ebWhh, ebb, Ws, bs, v,
                                       dWih, dWhh, db, Wout, bout, Wstop, bstop, out);
}

// round 7
// speedup vs baseline: 1.3905x; 1.3905x over previous
#include <cuda_runtime.h>

#define BB 32
#define TT 200
#define TM 400
#define EE 256
#define HH 256
#define ENCX 512
#define DECX 1024
#define OUTX 80

#define SOFF (BB*TM*OUTX)
#define AOFF (SOFF + BB*TM)

#define NCTA 148
#define NTHR 512

// decoder smem layout (floats)
#define WS_OFF 0                  // 28*1616 = 45248 gate weights
#define XS_OFF 45248              // 2 x 4096 staging buffers
#define V_OFF  (XS_OFF + 8192)    // 1024 attention v
#define GA_OFF (V_OFF + 1024)     // 896 gate accumulators
#define PD_OFF (GA_OFF + 896)     // 512 phase-D partials
#define SMEM_F (PD_OFF + 512)     // 55872 floats = 223488 B
#define SMEM_BYTES (SMEM_F*4)

// ---------------- device scratch ----------------
__device__ __align__(16) float g_enc_out[BB*TT*ENCX];
__device__ __align__(16) float g_proj[BB*TT*DECX];
__device__ __align__(16) float g_henc[2][2][HH*BB];
__device__ __align__(16) float g_cenc[2][HH*BB];
__device__ __align__(16) float g_hproj[BB*DECX];
__device__ __align__(16) float g_scores[BB*TT];
__device__ __align__(16) float g_ctx[ENCX*BB];
__device__ __align__(16) float g_hdec[2][DECX*BB];
__device__ __align__(16) float g_cdec[DECX*BB];

__device__ unsigned g_cnt = 0;
__device__ unsigned g_gen = 0;

__device__ __forceinline__ float sigf(float x) {
    return __fdividef(1.f, 1.f + __expf(-x));
}
__device__ __forceinline__ float tanhx(float x) {
    return 1.f - __fdividef(2.f, __expf(2.f * x) + 1.f);
}

__device__ __forceinline__ void gsync() {
    __syncthreads();
    if (threadIdx.x == 0) {
        __threadfence();
        unsigned g = g_gen;
        if (atomicAdd(&g_cnt, 1u) == gridDim.x - 1) {
            g_cnt = 0;
            __threadfence();
            atomicExch(&g_gen, g + 1u);
        } else {
            while (((volatile unsigned*)&g_gen)[0] == g) { }
        }
        __threadfence();
    }
    __syncthreads();
}

__global__ void __launch_bounds__(NTHR, 1) k_mega(
    const int* __restrict__ text, const float* __restrict__ melt,
    const float* __restrict__ emb,
    const float* __restrict__ efWih, const float* __restrict__ efWhh, const float* __restrict__ efb,
    const float* __restrict__ ebWih, const float* __restrict__ ebWhh, const float* __restrict__ ebb,
    const float* __restrict__ Ws, const float* __restrict__ bs, const float* __restrict__ v,
    const float* __restrict__ dWih, const float* __restrict__ dWhh, const float* __restrict__ db,
    const float* __restrict__ Wout, const float* __restrict__ bout,
    const float* __restrict__ Wstop, const float* __restrict__ bstop,
    float* __restrict__ out)
{
    extern __shared__ float sm[];
    const int cta  = blockIdx.x;
    const int tid  = threadIdx.x;
    const int w    = tid >> 5;
    const int lane = tid & 31;

    // ---------- zero states ----------
    {
        int gi = cta * NTHR + tid, gn = NCTA * NTHR;
        for (int j = gi; j < 2*2*HH*BB; j += gn) ((float*)g_henc)[j] = 0.f;
        for (int j = gi; j < 2*HH*BB;   j += gn) ((float*)g_cenc)[j] = 0.f;
        for (int j = gi; j < BB*DECX;   j += gn) g_hproj[j] = 0.f;
        for (int j = gi; j < 2*DECX*BB; j += gn) ((float*)g_hdec)[j] = 0.f;
        for (int j = gi; j < DECX*BB;   j += gn) g_cdec[j] = 0.f;
    }
    gsync();

    // ---------- encoder: 200 steps, CTAs 0..63, K split across warp halves ----------
    for (int t = 0; t < TT; t++) {
        if (cta < 64) {
            const int dir  = cta >> 5;
            const int bxx  = cta & 31;
            const int part = w >> 3;    // 0: x@Wih, 1: h@Whh
            const int wl   = w & 7;
            const int u    = bxx*8 + wl;
            const int p    = t & 1;
            const int tt   = dir ? (TT - 1 - t) : t;

            float* xs_e = sm;              // [256][33]
            float* hs_e = sm + 8448;       // [256][33]
            float* pa   = sm + 16896;      // [32][32]

            // stage x (warp stages b = 2w, 2w+1)
            #pragma unroll
            for (int r2 = 0; r2 < 2; r2++) {
                int b2  = w*2 + r2;
                int tok = text[b2 * TT + tt];
                #pragma unroll
                for (int kq = 0; kq < 2; kq++) {
                    float4 v4 = *(const float4*)(emb + tok*EE + kq*128 + lane*4);
                    int kb = kq*128 + lane*4;
                    xs_e[(kb+0)*33+b2] = v4.x; xs_e[(kb+1)*33+b2] = v4.y;
                    xs_e[(kb+2)*33+b2] = v4.z; xs_e[(kb+3)*33+b2] = v4.w;
                }
            }
            // stage h
            {
                const float4* s4 = (const float4*)g_henc[dir][p];
                for (int i2 = tid; i2 < 2048; i2 += NTHR) {
                    float4 v4 = __ldcg(s4 + i2);
                    int k = i2 >> 3, b4 = (i2 & 7) * 4;
                    hs_e[k*33+b4+0] = v4.x; hs_e[k*33+b4+1] = v4.y;
                    hs_e[k*33+b4+2] = v4.z; hs_e[k*33+b4+3] = v4.w;
                }
            }
            __syncthreads();

            const float* bias = dir ? ebb : efb;
            float a0, a1, a2, a3;
            if (part) { a0 = a1 = a2 = a3 = 0.f; }
            else { a0 = bias[u]; a1 = bias[HH+u]; a2 = bias[2*HH+u]; a3 = bias[3*HH+u]; }
            const float* W  = part ? (dir ? ebWhh : efWhh) : (dir ? ebWih : efWih);
            const float* w0 = W + u*EE;
            const float* w1 = W + (HH+u)*EE;
            const float* w2 = W + (2*HH+u)*EE;
            const float* w3 = W + (3*HH+u)*EE;
            const float* xp = part ? hs_e : xs_e;

            #pragma unroll 8
            for (int k = 0; k < 256; k += 4) {
                float x0 = xp[(k+0)*33+lane], x1 = xp[(k+1)*33+lane];
                float x2 = xp[(k+2)*33+lane], x3 = xp[(k+3)*33+lane];
                float4 q;
                q = *(const float4*)(w0+k); a0 += q.x*x0+q.y*x1+q.z*x2+q.w*x3;
                q = *(const float4*)(w1+k); a1 += q.x*x0+q.y*x1+q.z*x2+q.w*x3;
                q = *(const float4*)(w2+k); a2 += q.x*x0+q.y*x1+q.z*x2+q.w*x3;
                q = *(const float4*)(w3+k); a3 += q.x*x0+q.y*x1+q.z*x2+q.w*x3;
            }
            if (part) {
                pa[(wl*4+0)*32+lane] = a0; pa[(wl*4+1)*32+lane] = a1;
                pa[(wl*4+2)*32+lane] = a2; pa[(wl*4+3)*32+lane] = a3;
            }
            __syncthreads();
            if (!part) {
                a0 += pa[(wl*4+0)*32+lane]; a1 += pa[(wl*4+1)*32+lane];
                a2 += pa[(wl*4+2)*32+lane]; a3 += pa[(wl*4+3)*32+lane];
                float cc = g_cenc[dir][u*32 + lane];
                float cn = sigf(a1) * cc + sigf(a0) * tanhx(a2);
                float hn = sigf(a3) * tanhx(cn);
                g_cenc[dir][u*32 + lane] = cn;
                g_henc[dir][1 - p][u*32 + lane] = hn;
                g_enc_out[(lane*TT + tt)*ENCX + dir*HH + u] = hn;
            }
        }
        gsync();
    }

    // ---------- proj_enc GEMM: 1600 64x64 tiles over 148 CTAs ----------
    {
        float* As = sm;           // [16][65]
        float* Bs = sm + 1040;    // [16][65]
        const int tx = tid & 15, ty2 = tid >> 4;     // ty2 in [0,32): 2 rows each
        for (int tl = cta; tl < 1600; tl += NCTA) {
            const int n0 = (tl & 15) * 64, m0 = (tl >> 4) * 64;
            float acc[2][4];
            #pragma unroll
            for (int i = 0; i < 2; i++)
                #pragma unroll
                for (int j = 0; j < 4; j++) acc[i][j] = 0.f;
            for (int k0 = 0; k0 < ENCX; k0 += 16) {
                if (tid < 256) {
                    int rr = tid >> 2, q = tid & 3;
                    float4 a4 = *(const float4*)(g_enc_out + (m0 + rr)*ENCX + k0 + q*4);
                    As[(q*4+0)*65+rr] = a4.x; As[(q*4+1)*65+rr] = a4.y;
                    As[(q*4+2)*65+rr] = a4.z; As[(q*4+3)*65+rr] = a4.w;
                } else {
                    int t2 = tid - 256;
                    int rr = t2 >> 2, q = t2 & 3;
                    float4 b4 = *(const float4*)(Ws + (n0 + rr)*(ENCX+DECX) + k0 + q*4);
                    Bs[(q*4+0)*65+rr] = b4.x; Bs[(q*4+1)*65+rr] = b4.y;
                    Bs[(q*4+2)*65+rr] = b4.z; Bs[(q*4+3)*65+rr] = b4.w;
                }
                __syncthreads();
                #pragma unroll
                for (int k = 0; k < 16; k++) {
                    float ar0 = As[k*65 + ty2*2 + 0];
                    float ar1 = As[k*65 + ty2*2 + 1];
                    float br[4];
                    #pragma unroll
                    for (int j = 0; j < 4; j++) br[j] = Bs[k*65 + tx*4 + j];
                    #pragma unroll
                    for (int j = 0; j < 4; j++) { acc[0][j] += ar0*br[j]; acc[1][j] += ar1*br[j]; }
                }
                __syncthreads();
            }
            #pragma unroll
            for (int i = 0; i < 2; i++)
                #pragma unroll
                for (int j = 0; j < 4; j++)
                    g_proj[(m0 + ty2*2 + i)*DECX + n0 + tx*4 + j] = acc[i][j] + bs[n0 + tx*4 + j];
        }
        __syncthreads();
    }

    // ---------- preload decoder gate weights + v into smem ----------
    {
        for (int i = tid; i < 28*1616; i += NTHR) {
            int r = i / 1616, k = i - r*1616;
            int u = cta*7 + (r >> 2), g = r & 3;
            float val = 0.f;
            if (u < DECX)
                val = (k < 592) ? dWih[(g*DECX+u)*592 + k] : dWhh[(g*DECX+u)*DECX + (k-592)];
            sm[WS_OFF + i] = val;
        }
        for (int i = tid; i < DECX; i += NTHR) sm[V_OFF + i] = v[i];
        __syncthreads();
    }
    gsync();

    // ---------- decoder: 400 steps ----------
    float* xs0 = sm + XS_OFF;
    float* xs1 = xs0 + 4096;
    const float* vs = sm + V_OFF;

    for (int t = 0; t < TM; t++) {
        const int p = t & 1;

        // --- A: scores[b,s] ---
        for (int pp = cta*16 + w; pp < BB*TT; pp += NCTA*16) {
            const int b = pp & 31, s = pp >> 5;
            const float* pr = g_proj + (b*TT + s)*DECX;
            const float* hp = g_hproj + b*DECX;
            float acc = 0.f;
            #pragma unroll 4
            for (int d = lane; d < DECX; d += 32)
                acc += vs[d] * tanhx(pr[d] + __ldcg(hp + d));
            #pragma unroll
            for (int o = 16; o; o >>= 1) acc += __shfl_xor_sync(0xffffffffu, acc, o);
            if (lane == 0) g_scores[b*TT + s] = acc;
        }
        gsync();

        // --- B: softmax + context, 128 CTAs (b x 4 e-chunks) ---
        if (cta < 128) {
            const int b = cta >> 2, ec = cta & 3;
            float* wb  = xs0;          // [200]
            float* red = xs0 + 256;    // [512]
            float* pc  = xs0 + 768;    // [512]
            float m = -1e30f;
            if (tid < TT) m = __ldcg(g_scores + b*TT + tid);
            red[tid] = m; __syncthreads();
            for (int st = 256; st > 0; st >>= 1) {
                if (tid < st) red[tid] = fmaxf(red[tid], red[tid + st]);
                __syncthreads();
            }
            m = red[0]; __syncthreads();
            float sum = 0.f;
            if (tid < TT) {
                float e2 = __expf(__ldcg(g_scores + b*TT + tid) - m);
                wb[tid] = e2; sum = e2;
            }
            red[tid] = sum; __syncthreads();
            for (int st = 256; st > 0; st >>= 1) {
                if (tid < st) red[tid] += red[tid + st];
                __syncthreads();
            }
            float inv = __fdividef(1.f, red[0]);
            __syncthreads();
            if (tid < TT) {
                float ww = wb[tid] * inv; wb[tid] = ww;
                if (ec == 0) out[AOFF + (b*TM + t)*TT + tid] = ww;
            }
            __syncthreads();
            const int el = tid & 127, sq = tid >> 7;
            const int e = ec*128 + el;
            float c = 0.f;
            #pragma unroll 2
            for (int s = sq*50; s < sq*50 + 50; s++)
                c += wb[s] * g_enc_out[(b*TT + s)*ENCX + e];
            pc[sq*128 + el] = c;
            __syncthreads();
            if (tid < 128)
                g_ctx[(ec*128 + tid)*32 + b] = pc[tid] + pc[128+tid] + pc[256+tid] + pc[384+tid];
        }
        gsync();

        // --- C: gates GEMM + LSTM, 14 warps x 2 rows, double-buffered staging ---
        {
            // stage mel -> xs1, chunk1 (ctx 0) -> xs0
            for (int i = tid; i < 2560; i += NTHR) {
                int b2 = i & 31, e = i >> 5;
                xs1[i] = (t == 0) ? 0.f : melt[(b2*TM + (t-1))*OUTX + e];
            }
            {
                const float4* s4 = (const float4*)g_ctx;
                float4* d4 = (float4*)xs0;
                for (int i = tid; i < 1024; i += NTHR) d4[i] = __ldcg(s4 + i);
            }
            const int u = cta*7 + (w >> 1);
            const bool act = (w < 14) && (u < DECX);
            const float* wr0 = sm + WS_OFF + (2*w)*1616;
            const float* wr1 = wr0 + 1616;
            float A0 = 0.f, A1 = 0.f;
            if (act) {
                A0 = db[((2*w)   & 3)*DECX + u];
                A1 = db[((2*w+1) & 3)*DECX + u];
            }
            __syncthreads();
            if (act) {
                #pragma unroll 5
                for (int k = 0; k < OUTX; k += 4) {
                    float x0 = xs1[(k+0)*32+lane], x1 = xs1[(k+1)*32+lane];
                    float x2 = xs1[(k+2)*32+lane], x3 = xs1[(k+3)*32+lane];
                    float4 q0 = *(const float4*)(wr0+k);
                    float4 q1 = *(const float4*)(wr1+k);
                    A0 += q0.x*x0+q0.y*x1+q0.z*x2+q0.w*x3;
                    A1 += q1.x*x0+q1.y*x1+q1.z*x2+q1.w*x3;
                }
            }
            __syncthreads();
            for (int c = 1; c <= 12; c++) {
                float* cur = (c & 1) ? xs0 : xs1;
                float* nxt = (c & 1) ? xs1 : xs0;
                if (c < 12) {
                    const float* src = (c+1 <= 4) ? (g_ctx + c*4096)
                                                  : (g_hdec[p] + (c-4)*4096);
                    const float4* s4 = (const float4*)src;
                    float4* d4 = (float4*)nxt;
                    for (int i = tid; i < 1024; i += NTHR) d4[i] = __ldcg(s4 + i);
                }
                if (act) {
                    const int xo = OUTX + (c-1)*128;
                    #pragma unroll 8
                    for (int k = 0; k < 128; k += 4) {
                        float x0 = cur[(k+0)*32+lane], x1 = cur[(k+1)*32+lane];
                        float x2 = cur[(k+2)*32+lane], x3 = cur[(k+3)*32+lane];
                        float4 q0 = *(const float4*)(wr0+xo+k);
                        float4 q1 = *(const float4*)(wr1+xo+k);
                        A0 += q0.x*x0+q0.y*x1+q0.z*x2+q0.w*x3;
                        A1 += q1.x*x0+q1.y*x1+q1.z*x2+q1.w*x3;
                    }
                }
                __syncthreads();
            }
            float* ga = sm + GA_OFF;
            if (act) { ga[(2*w)*32+lane] = A0; ga[(2*w+1)*32+lane] = A1; }
            __syncthreads();
            if (tid < 224) {
                int u_l = tid >> 5, b2 = tid & 31;
                int uu = cta*7 + u_l;
                if (uu < DECX) {
                    float gi = ga[(u_l*4+0)*32+b2];
                    float gf = ga[(u_l*4+1)*32+b2];
                    float gg = ga[(u_l*4+2)*32+b2];
                    float go = ga[(u_l*4+3)*32+b2];
                    float cc = g_cdec[uu*32+b2];
                    float cn = sigf(gf)*cc + sigf(gi)*tanhx(gg);
                    float hn = sigf(go)*tanhx(cn);
                    g_cdec[uu*32+b2] = cn;
                    g_hdec[1-p][uu*32+b2] = hn;
                }
            }
        }
        gsync();

        // --- D: hproj / mel / stop; K split across warp halves ---
        {
            const int wl = w & 7, half = w >> 3;
            const int r = cta*8 + wl;
            const float* wrow = (r < DECX) ? (Ws + r*(ENCX+DECX) + ENCX)
                              : (r < DECX+OUTX) ? (Wout + (r-DECX)*DECX) : Wstop;
            const bool act = (r <= DECX + OUTX);
            float acc = 0.f;
            const float* hsrc = g_hdec[1 - p];
            for (int c = 0; c < 4; c++) {
                const float4* sA = (const float4*)(hsrc + c*4096);
                const float4* sB = (const float4*)(hsrc + (c+4)*4096);
                float4* dA = (float4*)xs0;
                float4* dB = (float4*)xs1;
                for (int i = tid; i < 1024; i += NTHR) { dA[i] = __ldcg(sA+i); dB[i] = __ldcg(sB+i); }
                __syncthreads();
                if (act) {
                    const float* xx = half ? xs1 : xs0;
                    const int ko = (half ? (c+4) : c) * 128;
                    #pragma unroll 8
                    for (int k = 0; k < 128; k += 4) {
                        float4 q = *(const float4*)(wrow + ko + k);
                        acc += q.x*xx[(k+0)*32+lane] + q.y*xx[(k+1)*32+lane]
                             + q.z*xx[(k+2)*32+lane] + q.w*xx[(k+3)*32+lane];
                    }
                }
                __syncthreads();
            }
            float* pd = sm + PD_OFF;
            pd[w*32 + lane] = acc;
            __syncthreads();
            if (w < 8) {
                float tot = pd[w*32+lane] + pd[(w+8)*32+lane];
                int rr = cta*8 + w;
                if (rr < DECX) g_hproj[lane*DECX + rr] = tot;
                else if (rr < DECX+OUTX) out[(lane*TM + t)*OUTX + (rr - DECX)] = tot + bout[rr - DECX];
                else if (rr == DECX+OUTX) out[SOFF + lane*TM + t] = sigf(tot + bstop[0]);
            }
        }
        gsync();
    }
}

extern "C" void kernel_launch(void* const* d_in, const int* in_sizes, int n_in,
                              void* d_out, int out_size)
{
    const int*   text  = (const int*)d_in[0];
    const float* melt  = (const float*)d_in[1];
    const float* emb   = (const float*)d_in[2];
    const float* efWih = (const float*)d_in[3];
    const float* efWhh = (const float*)d_in[4];
    const float* efb   = (const float*)d_in[5];
    const float* ebWih = (const float*)d_in[6];
    const float* ebWhh = (const float*)d_in[7];
    const float* ebb   = (const float*)d_in[8];
    const float* Ws    = (const float*)d_in[9];
    const float* bs    = (const float*)d_in[10];
    const float* v     = (const float*)d_in[11];
    const float* dWih  = (const float*)d_in[12];
    const float* dWhh  = (const float*)d_in[13];
    const float* db    = (const float*)d_in[14];
    const float* Wout  = (const float*)d_in[15];
    const float* bout  = (const float*)d_in[16];
    const float* Wstop = (const float*)d_in[17];
    const float* bstop = (const float*)d_in[18];
    float* out = (float*)d_out;

    static int smem_set = 0;
    if (!smem_set) {
        cudaFuncSetAttribute(k_mega, cudaFuncAttributeMaxDynamicSharedMemorySize, SMEM_BYTES);
        smem_set = 1;
    }
    k_mega<<<NCTA, NTHR, SMEM_BYTES>>>(text, melt, emb, efWih, efWhh, efb,
                                       ebWih, ebWhh, ebb, Ws, bs, v,
                                       dWih, dWhh, db, Wout, bout, Wstop, bstop, out);
}